// round 16
// baseline (speedup 1.0000x reference)
#include <cuda_runtime.h>
#include <cuda_pipeline.h>
#include <cuda_fp16.h>
#include <mma.h>
#include <cstdint>

using namespace nvcuda;

#define T_TOK 65536
#define H_DIM 1024
#define B_SEG 64
#define L_OUT 2

#define RS     64
#define NCHUNK (T_TOK / RS)        // 1024

// ---------------- scratch (device globals; no allocation allowed) ----------
__device__ __half g_h[(size_t)T_TOK * H_DIM];       // 128 MB fp16 h
__device__ __half g_xh[(size_t)T_TOK * H_DIM];      // 128 MB fp16 X
__device__ __half g_wh[(size_t)H_DIM * H_DIM];      // 2 MB fp16 W
__device__ float  g_psum[(size_t)T_TOK * 8];
__device__ float  g_psumsq[(size_t)T_TOK * 8];
__device__ int    g_starts[B_SEG + 1];
__device__ float  g_part[(size_t)B_SEG * NCHUNK * H_DIM];   // sparse-used

// ---------------- prepass: fp32 -> fp16 (X, W) + segment starts ------------
#define XCHUNKS (((size_t)T_TOK * H_DIM / 8) / 256)   // 32768 blocks for X
#define WCHUNKS (((size_t)H_DIM * H_DIM / 8) / 256)   // 512 blocks for W

__global__ void __launch_bounds__(256)
prepass_kernel(const float* __restrict__ X, const float* __restrict__ W,
               const int* __restrict__ seg) {
    size_t bid = blockIdx.x;
    if (bid >= XCHUNKS + WCHUNKS) {
        // segment starts
        int t = (int)(bid - XCHUNKS - WCHUNKS) * 256 + threadIdx.x;
        if (t >= T_TOK) return;
        if (t == 0) {
            g_starts[seg[0]] = 0;
            g_starts[B_SEG]  = T_TOK;
        } else if (seg[t] != seg[t - 1]) {
            g_starts[seg[t]] = t;
        }
        return;
    }
    const float* src;
    __half* dst;
    size_t i;
    if (bid < XCHUNKS) {
        i = (bid * 256 + threadIdx.x) * 8;
        src = X; dst = g_xh;
    } else {
        i = ((bid - XCHUNKS) * 256 + threadIdx.x) * 8;
        src = W; dst = g_wh;
    }
    float4 a = *(const float4*)&src[i];
    float4 b = *(const float4*)&src[i + 4];
    __half2 h[4];
    h[0] = __floats2half2_rn(a.x, a.y);
    h[1] = __floats2half2_rn(a.z, a.w);
    h[2] = __floats2half2_rn(b.x, b.y);
    h[3] = __floats2half2_rn(b.z, b.w);
    *(uint4*)&dst[i] = *(const uint4*)h;
}

// ---------------- K1: fp16 WMMA GEMM + bias + residual + fp16 h + stats ----
#define BM 128
#define BN 128
#define BK 64
#define LDA 72    // halfs: BK + 8
#define LDB 136   // halfs: BN + 8
#define LDC 136   // floats
#define NSTAGE 3
#define STAGEH (BM * LDA + BK * LDB)                 // 17920 halfs
#define SMEM_BYTES (NSTAGE * STAGEH * 2)             // 107520 B

__global__ void __launch_bounds__(256, 2)
gemm_bias_res_kernel(const float* __restrict__ bias,
                     const float* __restrict__ res) {
    extern __shared__ __half smem[];

    const int tid = threadIdx.x;
    const int wid = tid >> 5;
    const int warpM = wid & 3;
    const int warpN = wid >> 2;
    const int rowBase = blockIdx.y * BM;
    const int colBase = blockIdx.x * BN;
    const int aOff = warpM * 32 * LDA;
    const int bOff = warpN * 64;

    wmma::fragment<wmma::matrix_a, 16, 16, 16, __half, wmma::row_major> af[2];
    wmma::fragment<wmma::matrix_b, 16, 16, 16, __half, wmma::row_major> bf[4];
    wmma::fragment<wmma::accumulator, 16, 16, 16, float> cf[2][4];

    #pragma unroll
    for (int i = 0; i < 2; i++)
        #pragma unroll
        for (int j = 0; j < 4; j++)
            wmma::fill_fragment(cf[i][j], 0.0f);

    auto load_tile = [&](int kt, int buf) {
        __half* As = smem + buf * STAGEH;
        __half* Bs = As + BM * LDA;
        int k0 = kt * BK;
        // A: 128 rows x 64 halfs = 1024 chunks of 16B
        #pragma unroll
        for (int i = 0; i < 4; i++) {
            int idx = tid + i * 256;
            int r = idx >> 3, c8 = (idx & 7) * 8;
            __pipeline_memcpy_async(&As[r * LDA + c8],
                                    &g_xh[(size_t)(rowBase + r) * H_DIM + k0 + c8], 16);
        }
        // B: 64 rows x 128 halfs = 1024 chunks
        #pragma unroll
        for (int i = 0; i < 4; i++) {
            int idx = tid + i * 256;
            int r = idx >> 4, c8 = (idx & 15) * 8;
            __pipeline_memcpy_async(&Bs[r * LDB + c8],
                                    &g_wh[(size_t)(k0 + r) * H_DIM + colBase + c8], 16);
        }
    };

    const int NT = H_DIM / BK;   // 16
    load_tile(0, 0); __pipeline_commit();
    load_tile(1, 1); __pipeline_commit();

    for (int t = 0; t < NT; t++) {
        if (t + 1 < NT) __pipeline_wait_prior(1);
        else            __pipeline_wait_prior(0);
        __syncthreads();   // single barrier per tile; load target stage was
                           // last read at iter t-1 (fenced by this barrier)

        const __half* As = smem + (t % NSTAGE) * STAGEH;
        const __half* Bs = As + BM * LDA;
        #pragma unroll
        for (int kk = 0; kk < BK; kk += 16) {
            #pragma unroll
            for (int i = 0; i < 2; i++)
                wmma::load_matrix_sync(af[i], &As[aOff + i * 16 * LDA + kk], LDA);
            #pragma unroll
            for (int j = 0; j < 4; j++)
                wmma::load_matrix_sync(bf[j], &Bs[kk * LDB + bOff + j * 16], LDB);
            #pragma unroll
            for (int i = 0; i < 2; i++)
                #pragma unroll
                for (int j = 0; j < 4; j++)
                    wmma::mma_sync(cf[i][j], af[i], bf[j], cf[i][j]);
        }

        int tn = t + 2;
        if (tn < NT) { load_tile(tn, tn % NSTAGE); __pipeline_commit(); }
    }

    // ---- prefetch res for both epilogue phases into dead stages 1 & 2 ----
    // (stage 0 becomes Cs; stages 1/2 each hold 64x128 fp32 = 32768 B <= 35840 B)
    {
        #pragma unroll
        for (int p = 0; p < 2; p++) {
            float* rb = (float*)(smem + (1 + p) * STAGEH);
            #pragma unroll
            for (int i = 0; i < 8; i++) {
                int idx = tid + i * 256;       // 0..2047 16B chunks
                int r = idx >> 5;              // 0..63
                int c4 = (idx & 31) * 4;
                __pipeline_memcpy_async(rb + idx * 4,
                    &res[(size_t)(rowBase + p * 64 + r) * H_DIM + colBase + c4], 16);
            }
        }
        __pipeline_commit();
    }

    // ---- epilogue: two phases of 64 rows ----
    float* Cs = (float*)smem;   // [64][LDC] floats = 34816 B (stage 0)

    #pragma unroll
    for (int p = 0; p < 2; p++) {
        __syncthreads();
        if ((warpM >> 1) == p) {
            int rm = warpM & 1;
            #pragma unroll
            for (int i = 0; i < 2; i++)
                #pragma unroll
                for (int j = 0; j < 4; j++)
                    wmma::store_matrix_sync(&Cs[(rm * 32 + i * 16) * LDC + warpN * 64 + j * 16],
                                            cf[i][j], LDC, wmma::mem_row_major);
        }
        if (p == 0) __pipeline_wait_prior(0);   // res buffers ready
        __syncthreads();

        const float* rb = (const float*)(smem + (1 + p) * STAGEH);

        // bias + residual(smem); write fp16 h; keep fp32 in Cs for stats
        #pragma unroll
        for (int it = 0; it < 8; it++) {
            int idx = tid + it * 256;          // 0..2047 float4 slots
            int r = idx >> 5;                  // 0..63
            int c4 = (idx & 31) * 4;
            int grow = rowBase + p * 64 + r;
            size_t g = (size_t)grow * H_DIM + colBase + c4;
            float4 v = *(float4*)&Cs[r * LDC + c4];
            float4 rv = *(const float4*)&rb[r * 128 + c4];
            float4 bv = *(const float4*)&bias[colBase + c4];
            v.x += bv.x + rv.x;  v.y += bv.y + rv.y;
            v.z += bv.z + rv.z;  v.w += bv.w + rv.w;
            __half2 h01 = __floats2half2_rn(v.x, v.y);
            __half2 h23 = __floats2half2_rn(v.z, v.w);
            uint2 pk;
            pk.x = *(uint32_t*)&h01;
            pk.y = *(uint32_t*)&h23;
            *(uint2*)&g_h[g] = pk;
            *(float4*)&Cs[r * LDC + c4] = v;
        }
        __syncthreads();

        // row stats: 4 threads per row, 32 cols each
        {
            int r = tid >> 2;                  // 0..63
            int q = tid & 3;
            float s = 0.f, s2 = 0.f;
            #pragma unroll 4
            for (int c = 0; c < 32; c++) {
                float v = Cs[r * LDC + q * 32 + c];
                s += v;
                s2 += v * v;
            }
            s  += __shfl_xor_sync(0xFFFFFFFFu, s, 1);
            s2 += __shfl_xor_sync(0xFFFFFFFFu, s2, 1);
            s  += __shfl_xor_sync(0xFFFFFFFFu, s, 2);
            s2 += __shfl_xor_sync(0xFFFFFFFFu, s2, 2);
            if (q == 0) {
                int grow = rowBase + p * 64 + r;
                g_psum[(size_t)grow * 8 + blockIdx.x]   = s;
                g_psumsq[(size_t)grow * 8 + blockIdx.x] = s2;
            }
        }
    }
}

// ---------------- K3a: segpart with fused mu/rstd from psum partials -------
__global__ void __launch_bounds__(256)
segpart_kernel(const int* __restrict__ seg) {
    int chunk = blockIdx.x;
    int col2  = blockIdx.y * 512 + threadIdx.x * 2;
    int r0    = chunk * RS;

    __shared__ float smu[RS], srs[RS];
    __shared__ int   sseg[RS];
    // fused stats: 4 threads per row combine the 8 psum/psumsq partials
    {
        int i = threadIdx.x >> 2;              // row within chunk (0..63)
        int q = threadIdx.x & 3;               // partial pair index
        int row = r0 + i;
        float2 ps = *(const float2*)&g_psum[(size_t)row * 8 + q * 2];
        float2 qs = *(const float2*)&g_psumsq[(size_t)row * 8 + q * 2];
        float s  = ps.x + ps.y;
        float s2 = qs.x + qs.y;
        s  += __shfl_xor_sync(0xFFFFFFFFu, s, 1);
        s2 += __shfl_xor_sync(0xFFFFFFFFu, s2, 1);
        s  += __shfl_xor_sync(0xFFFFFFFFu, s, 2);
        s2 += __shfl_xor_sync(0xFFFFFFFFu, s2, 2);
        if (q == 0) {
            float mu  = s * (1.0f / H_DIM);
            float var = s2 * (1.0f / H_DIM) - mu * mu;
            smu[i] = mu;
            srs[i] = rsqrtf(var + 1e-12f);
        }
        if (q == 1) sseg[i] = seg[row];
    }
    __syncthreads();

    if (sseg[0] == sseg[RS - 1]) {
        float ax = 0.f, ay = 0.f, bx = 0.f, by = 0.f;
        #pragma unroll 4
        for (int i = 0; i < RS; i += 2) {
            __half2 v0 = *(const __half2*)&g_h[(size_t)(r0 + i) * H_DIM + col2];
            __half2 v1 = *(const __half2*)&g_h[(size_t)(r0 + i + 1) * H_DIM + col2];
            float2 f0 = __half22float2(v0);
            float2 f1 = __half22float2(v1);
            ax += (f0.x - smu[i]) * srs[i];
            ay += (f0.y - smu[i]) * srs[i];
            bx += (f1.x - smu[i + 1]) * srs[i + 1];
            by += (f1.y - smu[i + 1]) * srs[i + 1];
        }
        size_t o = ((size_t)sseg[0] * NCHUNK + chunk) * H_DIM + col2;
        g_part[o]     = ax + bx;
        g_part[o + 1] = ay + by;
        return;
    }

    float ax = 0.f, ay = 0.f;
    int cur = sseg[0];
    for (int i = 0; i < RS; i++) {
        int s = sseg[i];
        if (s != cur) {
            size_t o = ((size_t)cur * NCHUNK + chunk) * H_DIM + col2;
            g_part[o] = ax; g_part[o + 1] = ay;
            ax = 0.f; ay = 0.f;
            cur = s;
        }
        __half2 v = *(const __half2*)&g_h[(size_t)(r0 + i) * H_DIM + col2];
        float2 f = __half22float2(v);
        ax += (f.x - smu[i]) * srs[i];
        ay += (f.y - smu[i]) * srs[i];
    }
    size_t o = ((size_t)cur * NCHUNK + chunk) * H_DIM + col2;
    g_part[o] = ax; g_part[o + 1] = ay;
}

// ---------------- K4: chunk-reduce + affine + final projection -------------
__global__ void __launch_bounds__(256)
final_kernel(const float* __restrict__ gamma, const float* __restrict__ beta,
             const float* __restrict__ Wout, const float* __restrict__ bout,
             float* __restrict__ out) {
    int b = blockIdx.x;
    int tid = threadIdx.x;
    int s = g_starts[b], e = g_starts[b + 1];
    int c0 = s / RS, c1 = (e - 1) / RS;
    float inv = 1.0f / (float)(e - s);

    float p0 = 0.f, p1 = 0.f;
    for (int h = tid; h < H_DIM; h += 256) {
        float acc = 0.f;
        for (int c = c0; c <= c1; c++)
            acc += g_part[((size_t)b * NCHUNK + c) * H_DIM + h];
        float a = acc * inv * gamma[h] + beta[h];
        p0 += a * Wout[h * L_OUT + 0];
        p1 += a * Wout[h * L_OUT + 1];
    }
    __shared__ float r0[256], r1[256];
    r0[tid] = p0; r1[tid] = p1;
    __syncthreads();
    #pragma unroll
    for (int o = 128; o; o >>= 1) {
        if (tid < o) { r0[tid] += r0[tid + o]; r1[tid] += r1[tid + o]; }
        __syncthreads();
    }
    if (tid == 0) {
        out[b * L_OUT + 0] = r0[0] + bout[0];
        out[b * L_OUT + 1] = r1[0] + bout[1];
    }
}

// ---------------- launch ----------------
extern "C" void kernel_launch(void* const* d_in, const int* in_sizes, int n_in,
                              void* d_out, int out_size) {
    const float* X     = (const float*)d_in[0];
    const float* res   = (const float*)d_in[1];
    const float* Wd    = (const float*)d_in[2];
    const float* bias  = (const float*)d_in[3];
    const float* gamma = (const float*)d_in[4];
    const float* beta  = (const float*)d_in[5];
    const float* Wout  = (const float*)d_in[6];
    const float* bout  = (const float*)d_in[7];
    const int*   seg   = (const int*)d_in[8];
    float* out = (float*)d_out;

    cudaFuncSetAttribute(gemm_bias_res_kernel,
                         cudaFuncAttributeMaxDynamicSharedMemorySize, SMEM_BYTES);

    unsigned nprep = (unsigned)(XCHUNKS + WCHUNKS + T_TOK / 256);
    prepass_kernel<<<nprep, 256>>>(X, Wd, seg);

    dim3 g1(H_DIM / BN, T_TOK / BM);     // col-block fast -> X strips stay in L2
    gemm_bias_res_kernel<<<g1, 256, SMEM_BYTES>>>(bias, res);

    dim3 g3(NCHUNK, H_DIM / 512);
    segpart_kernel<<<g3, 256>>>(seg);

    final_kernel<<<B_SEG, 256>>>(gamma, beta, Wout, bout, out);
}

// round 17
// speedup vs baseline: 1.0346x; 1.0346x over previous
#include <cuda_runtime.h>
#include <cuda_pipeline.h>
#include <cuda_fp16.h>
#include <mma.h>
#include <cstdint>

using namespace nvcuda;

#define T_TOK 65536
#define H_DIM 1024
#define B_SEG 64
#define L_OUT 2

#define RS     64
#define NCHUNK (T_TOK / RS)        // 1024

// ---------------- scratch (device globals; no allocation allowed) ----------
__device__ __half g_h[(size_t)T_TOK * H_DIM];       // 128 MB fp16 h
__device__ __half g_xh[(size_t)T_TOK * H_DIM];      // 128 MB fp16 X
__device__ __half g_wh[(size_t)H_DIM * H_DIM];      // 2 MB fp16 W
__device__ float  g_psum[(size_t)T_TOK * 8];
__device__ float  g_psumsq[(size_t)T_TOK * 8];
__device__ int    g_starts[B_SEG + 1];
__device__ float  g_part[(size_t)B_SEG * NCHUNK * H_DIM];   // sparse-used
__device__ float  g_segmean[B_SEG * H_DIM];

// ---------------- prepass: fp32 -> fp16 (X, W) + segment starts ------------
#define XCHUNKS (((size_t)T_TOK * H_DIM / 8) / 256)   // 32768 blocks for X
#define WCHUNKS (((size_t)H_DIM * H_DIM / 8) / 256)   // 512 blocks for W

__global__ void __launch_bounds__(256)
prepass_kernel(const float* __restrict__ X, const float* __restrict__ W,
               const int* __restrict__ seg) {
    size_t bid = blockIdx.x;
    if (bid >= XCHUNKS + WCHUNKS) {
        // segment starts
        int t = (int)(bid - XCHUNKS - WCHUNKS) * 256 + threadIdx.x;
        if (t >= T_TOK) return;
        if (t == 0) {
            g_starts[seg[0]] = 0;
            g_starts[B_SEG]  = T_TOK;
        } else if (seg[t] != seg[t - 1]) {
            g_starts[seg[t]] = t;
        }
        return;
    }
    const float* src;
    __half* dst;
    size_t i;
    if (bid < XCHUNKS) {
        i = (bid * 256 + threadIdx.x) * 8;
        src = X; dst = g_xh;
    } else {
        i = ((bid - XCHUNKS) * 256 + threadIdx.x) * 8;
        src = W; dst = g_wh;
    }
    float4 a = *(const float4*)&src[i];
    float4 b = *(const float4*)&src[i + 4];
    __half2 h[4];
    h[0] = __floats2half2_rn(a.x, a.y);
    h[1] = __floats2half2_rn(a.z, a.w);
    h[2] = __floats2half2_rn(b.x, b.y);
    h[3] = __floats2half2_rn(b.z, b.w);
    *(uint4*)&dst[i] = *(const uint4*)h;
}

// ---------------- K1: fp16 WMMA GEMM + bias + residual + fp16 h + stats ----
#define BM 128
#define BN 128
#define BK 64
#define LDA 72    // halfs: BK + 8
#define LDB 136   // halfs: BN + 8
#define LDC 136   // floats
#define NSTAGE 3
#define STAGEH (BM * LDA + BK * LDB)                 // 17920 halfs
#define SMEM_BYTES (NSTAGE * STAGEH * 2)             // 107520 B

__global__ void __launch_bounds__(256, 2)
gemm_bias_res_kernel(const float* __restrict__ bias,
                     const float* __restrict__ res) {
    extern __shared__ __half smem[];

    const int tid = threadIdx.x;
    const int wid = tid >> 5;
    const int warpM = wid & 3;
    const int warpN = wid >> 2;
    const int rowBase = blockIdx.y * BM;
    const int colBase = blockIdx.x * BN;
    const int aOff = warpM * 32 * LDA;
    const int bOff = warpN * 64;

    wmma::fragment<wmma::matrix_a, 16, 16, 16, __half, wmma::row_major> af[2];
    wmma::fragment<wmma::matrix_b, 16, 16, 16, __half, wmma::row_major> bf[4];
    wmma::fragment<wmma::accumulator, 16, 16, 16, float> cf[2][4];

    #pragma unroll
    for (int i = 0; i < 2; i++)
        #pragma unroll
        for (int j = 0; j < 4; j++)
            wmma::fill_fragment(cf[i][j], 0.0f);

    auto load_tile = [&](int kt, int buf) {
        __half* As = smem + buf * STAGEH;
        __half* Bs = As + BM * LDA;
        int k0 = kt * BK;
        // A: 128 rows x 64 halfs = 1024 chunks of 16B
        #pragma unroll
        for (int i = 0; i < 4; i++) {
            int idx = tid + i * 256;
            int r = idx >> 3, c8 = (idx & 7) * 8;
            __pipeline_memcpy_async(&As[r * LDA + c8],
                                    &g_xh[(size_t)(rowBase + r) * H_DIM + k0 + c8], 16);
        }
        // B: 64 rows x 128 halfs = 1024 chunks
        #pragma unroll
        for (int i = 0; i < 4; i++) {
            int idx = tid + i * 256;
            int r = idx >> 4, c8 = (idx & 15) * 8;
            __pipeline_memcpy_async(&Bs[r * LDB + c8],
                                    &g_wh[(size_t)(k0 + r) * H_DIM + colBase + c8], 16);
        }
    };

    const int NT = H_DIM / BK;   // 16
    load_tile(0, 0); __pipeline_commit();
    load_tile(1, 1); __pipeline_commit();

    for (int t = 0; t < NT; t++) {
        if (t + 1 < NT) __pipeline_wait_prior(1);
        else            __pipeline_wait_prior(0);
        __syncthreads();   // single barrier per tile; load target stage was
                           // last read at iter t-1 (fenced by this barrier)

        const __half* As = smem + (t % NSTAGE) * STAGEH;
        const __half* Bs = As + BM * LDA;
        #pragma unroll
        for (int kk = 0; kk < BK; kk += 16) {
            #pragma unroll
            for (int i = 0; i < 2; i++)
                wmma::load_matrix_sync(af[i], &As[aOff + i * 16 * LDA + kk], LDA);
            #pragma unroll
            for (int j = 0; j < 4; j++)
                wmma::load_matrix_sync(bf[j], &Bs[kk * LDB + bOff + j * 16], LDB);
            #pragma unroll
            for (int i = 0; i < 2; i++)
                #pragma unroll
                for (int j = 0; j < 4; j++)
                    wmma::mma_sync(cf[i][j], af[i], bf[j], cf[i][j]);
        }

        int tn = t + 2;
        if (tn < NT) { load_tile(tn, tn % NSTAGE); __pipeline_commit(); }
    }

    // ---- prefetch res for both epilogue phases into dead stages 1 & 2 ----
    {
        #pragma unroll
        for (int p = 0; p < 2; p++) {
            float* rb = (float*)(smem + (1 + p) * STAGEH);
            #pragma unroll
            for (int i = 0; i < 8; i++) {
                int idx = tid + i * 256;       // 0..2047 16B chunks
                int r = idx >> 5;              // 0..63
                int c4 = (idx & 31) * 4;
                __pipeline_memcpy_async(rb + idx * 4,
                    &res[(size_t)(rowBase + p * 64 + r) * H_DIM + colBase + c4], 16);
            }
        }
        __pipeline_commit();
    }

    // ---- epilogue: two phases of 64 rows ----
    float* Cs = (float*)smem;   // [64][LDC] floats = 34816 B (stage 0)

    #pragma unroll
    for (int p = 0; p < 2; p++) {
        __syncthreads();
        if ((warpM >> 1) == p) {
            int rm = warpM & 1;
            #pragma unroll
            for (int i = 0; i < 2; i++)
                #pragma unroll
                for (int j = 0; j < 4; j++)
                    wmma::store_matrix_sync(&Cs[(rm * 32 + i * 16) * LDC + warpN * 64 + j * 16],
                                            cf[i][j], LDC, wmma::mem_row_major);
        }
        if (p == 0) __pipeline_wait_prior(0);   // res buffers ready
        __syncthreads();

        const float* rb = (const float*)(smem + (1 + p) * STAGEH);

        // bias + residual(smem); write fp16 h; keep fp32 in Cs for stats
        #pragma unroll
        for (int it = 0; it < 8; it++) {
            int idx = tid + it * 256;          // 0..2047 float4 slots
            int r = idx >> 5;                  // 0..63
            int c4 = (idx & 31) * 4;
            int grow = rowBase + p * 64 + r;
            size_t g = (size_t)grow * H_DIM + colBase + c4;
            float4 v = *(float4*)&Cs[r * LDC + c4];
            float4 rv = *(const float4*)&rb[r * 128 + c4];
            float4 bv = *(const float4*)&bias[colBase + c4];
            v.x += bv.x + rv.x;  v.y += bv.y + rv.y;
            v.z += bv.z + rv.z;  v.w += bv.w + rv.w;
            __half2 h01 = __floats2half2_rn(v.x, v.y);
            __half2 h23 = __floats2half2_rn(v.z, v.w);
            uint2 pk;
            pk.x = *(uint32_t*)&h01;
            pk.y = *(uint32_t*)&h23;
            *(uint2*)&g_h[g] = pk;
            *(float4*)&Cs[r * LDC + c4] = v;
        }
        __syncthreads();

        // row stats: 4 threads per row, 32 cols each
        {
            int r = tid >> 2;                  // 0..63
            int q = tid & 3;
            float s = 0.f, s2 = 0.f;
            #pragma unroll 4
            for (int c = 0; c < 32; c++) {
                float v = Cs[r * LDC + q * 32 + c];
                s += v;
                s2 += v * v;
            }
            s  += __shfl_xor_sync(0xFFFFFFFFu, s, 1);
            s2 += __shfl_xor_sync(0xFFFFFFFFu, s2, 1);
            s  += __shfl_xor_sync(0xFFFFFFFFu, s, 2);
            s2 += __shfl_xor_sync(0xFFFFFFFFu, s2, 2);
            if (q == 0) {
                int grow = rowBase + p * 64 + r;
                g_psum[(size_t)grow * 8 + blockIdx.x]   = s;
                g_psumsq[(size_t)grow * 8 + blockIdx.x] = s2;
            }
        }
    }
}

// ---------------- K3a: segpart with fused mu/rstd from psum partials -------
__global__ void __launch_bounds__(256)
segpart_kernel(const int* __restrict__ seg) {
    int chunk = blockIdx.x;
    int col2  = blockIdx.y * 512 + threadIdx.x * 2;
    int r0    = chunk * RS;

    __shared__ float smu[RS], srs[RS];
    __shared__ int   sseg[RS];
    // fused stats: 4 threads per row combine the 8 psum/psumsq partials
    {
        int i = threadIdx.x >> 2;              // row within chunk (0..63)
        int q = threadIdx.x & 3;               // partial pair index
        int row = r0 + i;
        float2 ps = *(const float2*)&g_psum[(size_t)row * 8 + q * 2];
        float2 qs = *(const float2*)&g_psumsq[(size_t)row * 8 + q * 2];
        float s  = ps.x + ps.y;
        float s2 = qs.x + qs.y;
        s  += __shfl_xor_sync(0xFFFFFFFFu, s, 1);
        s2 += __shfl_xor_sync(0xFFFFFFFFu, s2, 1);
        s  += __shfl_xor_sync(0xFFFFFFFFu, s, 2);
        s2 += __shfl_xor_sync(0xFFFFFFFFu, s2, 2);
        if (q == 0) {
            float mu  = s * (1.0f / H_DIM);
            float var = s2 * (1.0f / H_DIM) - mu * mu;
            smu[i] = mu;
            srs[i] = rsqrtf(var + 1e-12f);
        }
        if (q == 1) sseg[i] = seg[row];
    }
    __syncthreads();

    if (sseg[0] == sseg[RS - 1]) {
        float ax = 0.f, ay = 0.f, bx = 0.f, by = 0.f;
        #pragma unroll 4
        for (int i = 0; i < RS; i += 2) {
            __half2 v0 = *(const __half2*)&g_h[(size_t)(r0 + i) * H_DIM + col2];
            __half2 v1 = *(const __half2*)&g_h[(size_t)(r0 + i + 1) * H_DIM + col2];
            float2 f0 = __half22float2(v0);
            float2 f1 = __half22float2(v1);
            ax += (f0.x - smu[i]) * srs[i];
            ay += (f0.y - smu[i]) * srs[i];
            bx += (f1.x - smu[i + 1]) * srs[i + 1];
            by += (f1.y - smu[i + 1]) * srs[i + 1];
        }
        size_t o = ((size_t)sseg[0] * NCHUNK + chunk) * H_DIM + col2;
        g_part[o]     = ax + bx;
        g_part[o + 1] = ay + by;
        return;
    }

    float ax = 0.f, ay = 0.f;
    int cur = sseg[0];
    for (int i = 0; i < RS; i++) {
        int s = sseg[i];
        if (s != cur) {
            size_t o = ((size_t)cur * NCHUNK + chunk) * H_DIM + col2;
            g_part[o] = ax; g_part[o + 1] = ay;
            ax = 0.f; ay = 0.f;
            cur = s;
        }
        __half2 v = *(const __half2*)&g_h[(size_t)(r0 + i) * H_DIM + col2];
        float2 f = __half22float2(v);
        ax += (f.x - smu[i]) * srs[i];
        ay += (f.y - smu[i]) * srs[i];
    }
    size_t o = ((size_t)cur * NCHUNK + chunk) * H_DIM + col2;
    g_part[o] = ax; g_part[o + 1] = ay;
}

// ---------------- K3b: reduce -> segment means ----------------
__global__ void __launch_bounds__(256)
segreduce_kernel() {
    int b   = blockIdx.x;
    int col = blockIdx.y * 256 + threadIdx.x;
    int s = g_starts[b], e = g_starts[b + 1];
    int c0 = s / RS, c1 = (e - 1) / RS;
    float acc = 0.f;
    for (int c = c0; c <= c1; c++)
        acc += g_part[((size_t)b * NCHUNK + c) * H_DIM + col];
    g_segmean[b * H_DIM + col] = acc * (1.0f / (float)(e - s));
}

// ---------------- K4: affine + final projection ----------------
__global__ void __launch_bounds__(256)
final_kernel(const float* __restrict__ gamma, const float* __restrict__ beta,
             const float* __restrict__ Wout, const float* __restrict__ bout,
             float* __restrict__ out) {
    int b = blockIdx.x;
    int tid = threadIdx.x;
    float p0 = 0.f, p1 = 0.f;
    for (int h = tid; h < H_DIM; h += 256) {
        float a = g_segmean[b * H_DIM + h] * gamma[h] + beta[h];
        p0 += a * Wout[h * L_OUT + 0];
        p1 += a * Wout[h * L_OUT + 1];
    }
    __shared__ float r0[256], r1[256];
    r0[tid] = p0; r1[tid] = p1;
    __syncthreads();
    #pragma unroll
    for (int o = 128; o; o >>= 1) {
        if (tid < o) { r0[tid] += r0[tid + o]; r1[tid] += r1[tid + o]; }
        __syncthreads();
    }
    if (tid == 0) {
        out[b * L_OUT + 0] = r0[0] + bout[0];
        out[b * L_OUT + 1] = r1[0] + bout[1];
    }
}

// ---------------- launch ----------------
extern "C" void kernel_launch(void* const* d_in, const int* in_sizes, int n_in,
                              void* d_out, int out_size) {
    const float* X     = (const float*)d_in[0];
    const float* res   = (const float*)d_in[1];
    const float* Wd    = (const float*)d_in[2];
    const float* bias  = (const float*)d_in[3];
    const float* gamma = (const float*)d_in[4];
    const float* beta  = (const float*)d_in[5];
    const float* Wout  = (const float*)d_in[6];
    const float* bout  = (const float*)d_in[7];
    const int*   seg   = (const int*)d_in[8];
    float* out = (float*)d_out;

    cudaFuncSetAttribute(gemm_bias_res_kernel,
                         cudaFuncAttributeMaxDynamicSharedMemorySize, SMEM_BYTES);

    unsigned nprep = (unsigned)(XCHUNKS + WCHUNKS + T_TOK / 256);
    prepass_kernel<<<nprep, 256>>>(X, Wd, seg);

    dim3 g1(H_DIM / BN, T_TOK / BM);     // col-block fast -> X strips stay in L2
    gemm_bias_res_kernel<<<g1, 256, SMEM_BYTES>>>(bias, res);

    dim3 g3(NCHUNK, H_DIM / 512);
    segpart_kernel<<<g3, 256>>>(seg);

    dim3 g4(B_SEG, H_DIM / 256);
    segreduce_kernel<<<g4, 256>>>();

    final_kernel<<<B_SEG, 256>>>(gamma, beta, Wout, bout, out);
}